// round 3
// baseline (speedup 1.0000x reference)
#include <cuda_runtime.h>
#include <cuda_bf16.h>

#define N_NODES 50000
#define D 32
#define D4 8
#define EMAX 1600000

// Scratch (device globals — no allocation allowed).
__device__ float g_seg[N_NODES * D];    // node_mean
__device__ float g_g[N_NODES * D];      // g = h @ W.T
__device__ int   g_deg[N_NODES];        // in-degree (int)
__device__ int   g_row[N_NODES];        // CSR row offsets (exclusive)
__device__ int   g_cur[N_NODES];        // fill cursors
__device__ int   g_csr_e[EMAX];         // edge id per CSR slot (for ef rows)
__device__ int   g_csr_src[EMAX];       // src node per CSR slot (for step 2)

// ---------------------------------------------------------------------------
// K1: zero degree counters
// ---------------------------------------------------------------------------
__global__ void k_init() {
    int i = blockIdx.x * blockDim.x + threadIdx.x;
    if (i < N_NODES) g_deg[i] = 0;
}

// ---------------------------------------------------------------------------
// K2: count in-degrees
// ---------------------------------------------------------------------------
__global__ void k_count(const int* __restrict__ dst, int E) {
    int e = blockIdx.x * blockDim.x + threadIdx.x;
    if (e < E) atomicAdd(&g_deg[dst[e]], 1);
}

// ---------------------------------------------------------------------------
// K3: exclusive scan of degrees -> row offsets + cursors (single block)
// ---------------------------------------------------------------------------
__global__ void k_scan() {
    __shared__ int sm[1024];
    int tid = threadIdx.x;
    const int CH = (N_NODES + 1023) / 1024;        // 49
    int base = tid * CH;
    int end  = min(base + CH, N_NODES);
    int s = 0;
    for (int i = base; i < end; i++) s += g_deg[i];
    sm[tid] = s;
    __syncthreads();
    for (int d = 1; d < 1024; d <<= 1) {           // Hillis-Steele inclusive
        int v = (tid >= d) ? sm[tid - d] : 0;
        __syncthreads();
        sm[tid] += v;
        __syncthreads();
    }
    int off = sm[tid] - s;                         // exclusive
    for (int i = base; i < end; i++) {
        g_row[i] = off;
        g_cur[i] = off;
        off += g_deg[i];
    }
}

// ---------------------------------------------------------------------------
// K4: fill CSR (edge id + src id per slot)
// ---------------------------------------------------------------------------
__global__ void k_fill(const int* __restrict__ src,
                       const int* __restrict__ dst, int E) {
    int e = blockIdx.x * blockDim.x + threadIdx.x;
    if (e >= E) return;
    int p = atomicAdd(&g_cur[dst[e]], 1);
    g_csr_e[p]   = e;
    g_csr_src[p] = src[e];
}

// ---------------------------------------------------------------------------
// K5: node_mean[n] = mean of ef rows of in-edges. Warp per node, lane per dim.
// Each row load = one 128B coalesced wavefront. No atomics, plain store.
// ---------------------------------------------------------------------------
__global__ void k_node_mean(const float* __restrict__ ef) {
    int w = (blockIdx.x * blockDim.x + threadIdx.x) >> 5;
    if (w >= N_NODES) return;
    int lane  = threadIdx.x & 31;
    int start = g_row[w];
    int cnt   = g_deg[w];
    float acc = 0.0f;
    int i = 0;
    for (; i + 4 <= cnt; i += 4) {                 // 4-way ILP
        int e0 = g_csr_e[start + i];
        int e1 = g_csr_e[start + i + 1];
        int e2 = g_csr_e[start + i + 2];
        int e3 = g_csr_e[start + i + 3];
        float a0 = ef[e0 * D + lane];
        float a1 = ef[e1 * D + lane];
        float a2 = ef[e2 * D + lane];
        float a3 = ef[e3 * D + lane];
        acc += (a0 + a1) + (a2 + a3);
    }
    for (; i < cnt; i++)
        acc += ef[g_csr_e[start + i] * D + lane];
    g_seg[w * D + lane] = acc / fmaxf((float)cnt, 1.0f);
}

// ---------------------------------------------------------------------------
// K6: h[n] = sum of node_mean[src] rows over in-edges, then g = h @ W.T.
// Warp per node; h row staged in smem for the warp-local 32x32 dot.
// ---------------------------------------------------------------------------
__global__ void k_node_h_gemm(const float* __restrict__ W) {
    __shared__ float Ws[D * (D + 1)];
    __shared__ float hs[8][D];                     // 8 warps / 256-thread block
    for (int i = threadIdx.x; i < D * D; i += blockDim.x)
        Ws[(i / D) * (D + 1) + (i % D)] = W[i];
    __syncthreads();

    int w = (blockIdx.x * blockDim.x + threadIdx.x) >> 5;
    if (w >= N_NODES) return;
    int lane  = threadIdx.x & 31;
    int wib   = (threadIdx.x >> 5) & 7;
    int start = g_row[w];
    int cnt   = g_deg[w];
    float acc = 0.0f;
    int i = 0;
    for (; i + 4 <= cnt; i += 4) {
        int s0 = g_csr_src[start + i];
        int s1 = g_csr_src[start + i + 1];
        int s2 = g_csr_src[start + i + 2];
        int s3 = g_csr_src[start + i + 3];
        float a0 = g_seg[s0 * D + lane];           // L2-resident rows
        float a1 = g_seg[s1 * D + lane];
        float a2 = g_seg[s2 * D + lane];
        float a3 = g_seg[s3 * D + lane];
        acc += (a0 + a1) + (a2 + a3);
    }
    for (; i < cnt; i++)
        acc += g_seg[g_csr_src[start + i] * D + lane];

    hs[wib][lane] = acc;                           // h row for this node
    __syncwarp();
    float gacc = 0.0f;
#pragma unroll
    for (int k = 0; k < D; k++)
        gacc = fmaf(hs[wib][k], Ws[lane * (D + 1) + k], gacc);
    g_g[w * D + lane] = gacc;
}

// ---------------------------------------------------------------------------
// K7: out[e] = 0.5*(g[src[e]] + g[dst[e]]) + b   (float4; g is L2-resident)
// ---------------------------------------------------------------------------
__global__ void k_edge_out(const int* __restrict__ src,
                           const int* __restrict__ dst,
                           const float* __restrict__ b,
                           float4* __restrict__ out, int E) {
    __shared__ float4 bs[D4];
    if (threadIdx.x < D4)
        bs[threadIdx.x] = *(const float4*)&b[threadIdx.x * 4];
    __syncthreads();
    int t = blockIdx.x * blockDim.x + threadIdx.x;
    if (t >= E * D4) return;
    int e  = t >> 3;
    int d4 = t & 7;
    int ns = src[e];
    int nd = dst[e];
    float4 a = *(const float4*)&g_g[ns * D + d4 * 4];
    float4 c = *(const float4*)&g_g[nd * D + d4 * 4];
    float4 bb = bs[d4];
    float4 o;
    o.x = fmaf(0.5f, a.x + c.x, bb.x);
    o.y = fmaf(0.5f, a.y + c.y, bb.y);
    o.z = fmaf(0.5f, a.z + c.z, bb.z);
    o.w = fmaf(0.5f, a.w + c.w, bb.w);
    out[t] = o;
}

// ---------------------------------------------------------------------------
// Launch
// ---------------------------------------------------------------------------
extern "C" void kernel_launch(void* const* d_in, const int* in_sizes, int n_in,
                              void* d_out, int out_size) {
    const float* edge_feats = (const float*)d_in[0];
    const int*   src        = (const int*)d_in[1];
    const int*   dst        = (const int*)d_in[2];
    const float* W          = (const float*)d_in[3];
    const float* b          = (const float*)d_in[4];

    const int E   = in_sizes[1];
    const int TPB = 256;

    k_init<<<(N_NODES + TPB - 1) / TPB, TPB>>>();
    k_count<<<(E + TPB - 1) / TPB, TPB>>>(dst, E);
    k_scan<<<1, 1024>>>();
    k_fill<<<(E + TPB - 1) / TPB, TPB>>>(src, dst, E);

    const int node_threads = N_NODES * 32;         // warp per node
    k_node_mean<<<(node_threads + TPB - 1) / TPB, TPB>>>(edge_feats);
    k_node_h_gemm<<<(node_threads + TPB - 1) / TPB, TPB>>>(W);

    const int edge_v4 = E * D4;
    k_edge_out<<<(edge_v4 + TPB - 1) / TPB, TPB>>>(src, dst, b, (float4*)d_out, E);
}

// round 4
// speedup vs baseline: 1.6198x; 1.6198x over previous
#include <cuda_runtime.h>
#include <cuda_bf16.h>

#define N_NODES 50000
#define D 32
#define D4 8

// Scratch (device globals — no allocation allowed).
__device__ float g_seg[N_NODES * D];   // step1 accumulator -> m*W^T (in place)
__device__ float g_deg[N_NODES];       // in-degree
__device__ float g_g[N_NODES * D];     // init b, += (m W^T)[src] -> g + b

__device__ __forceinline__ void red_add_v4(float* ptr, float4 v) {
    asm volatile("red.global.add.v4.f32 [%0], {%1, %2, %3, %4};"
                 :: "l"(ptr), "f"(v.x), "f"(v.y), "f"(v.z), "f"(v.w)
                 : "memory");
}

__device__ __forceinline__ void st_cs_v4(float4* ptr, float4 v) {
    asm volatile("st.global.cs.v4.f32 [%0], {%1, %2, %3, %4};"
                 :: "l"(ptr), "f"(v.x), "f"(v.y), "f"(v.z), "f"(v.w)
                 : "memory");
}

// ---------------------------------------------------------------------------
// K1: g_seg = 0, deg = 0, g_g rows = b (bias folded into accumulator init)
// ---------------------------------------------------------------------------
__global__ void k_zero(const float* __restrict__ b) {
    int i = blockIdx.x * blockDim.x + threadIdx.x;   // over N_NODES * D4
    if (i < N_NODES * D4) {
        ((float4*)g_seg)[i] = make_float4(0.f, 0.f, 0.f, 0.f);
        ((float4*)g_g)[i]   = *(const float4*)&b[(i & 7) * 4];
    }
    if (i < N_NODES) g_deg[i] = 0.0f;
}

// ---------------------------------------------------------------------------
// K2: seg_sum[dst] += edge_feats[e]; deg[dst] += 1.  8 threads/edge, float4.
// ---------------------------------------------------------------------------
__global__ void k_scatter_feats(const float4* __restrict__ ef,
                                const int* __restrict__ dst, int E) {
    int t = blockIdx.x * blockDim.x + threadIdx.x;   // over E * D4
    if (t >= E * D4) return;
    int e  = t >> 3;
    int d4 = t & 7;
    float4 v = ef[t];
    int n = dst[e];
    red_add_v4(&g_seg[n * D + d4 * 4], v);
    if (d4 == 0) atomicAdd(&g_deg[n], 1.0f);
}

// ---------------------------------------------------------------------------
// K3: m = seg/max(deg,1); then g_seg row <- m @ W^T (warp per node).
// W cached in smem with +1 pad; m row staged in smem per warp.
// ---------------------------------------------------------------------------
__global__ void k_norm_gemm(const float* __restrict__ W) {
    __shared__ float Ws[D * (D + 1)];
    __shared__ float ms[8][D];                       // 8 warps / 256 threads
    for (int i = threadIdx.x; i < D * D; i += blockDim.x)
        Ws[(i / D) * (D + 1) + (i % D)] = W[i];
    __syncthreads();

    int w = (blockIdx.x * blockDim.x + threadIdx.x) >> 5;
    if (w >= N_NODES) return;
    int lane = threadIdx.x & 31;
    int wib  = (threadIdx.x >> 5) & 7;

    float inv = 1.0f / fmaxf(g_deg[w], 1.0f);
    float m   = g_seg[w * D + lane] * inv;
    ms[wib][lane] = m;
    __syncwarp();
    float acc = 0.0f;
#pragma unroll
    for (int k = 0; k < D; k++)
        acc = fmaf(ms[wib][k], Ws[lane * (D + 1) + k], acc);
    g_seg[w * D + lane] = acc;                       // in place: row fully read above
}

// ---------------------------------------------------------------------------
// K4: g_g[dst] += (mW)[src]    (gather float4 from L2, vector-red)
// ---------------------------------------------------------------------------
__global__ void k_gather_scatter(const int* __restrict__ src,
                                 const int* __restrict__ dst, int E) {
    int t = blockIdx.x * blockDim.x + threadIdx.x;   // over E * D4
    if (t >= E * D4) return;
    int e  = t >> 3;
    int d4 = t & 7;
    int ns = src[e];
    int nd = dst[e];
    float4 v = *(const float4*)&g_seg[ns * D + d4 * 4];
    red_add_v4(&g_g[nd * D + d4 * 4], v);
}

// ---------------------------------------------------------------------------
// K5: out[e] = 0.5*(g_g[src[e]] + g_g[dst[e]])   (bias already inside g_g)
// ---------------------------------------------------------------------------
__global__ void k_edge_out(const int* __restrict__ src,
                           const int* __restrict__ dst,
                           float4* __restrict__ out, int E) {
    int t = blockIdx.x * blockDim.x + threadIdx.x;   // over E * D4
    if (t >= E * D4) return;
    int e  = t >> 3;
    int d4 = t & 7;
    int ns = src[e];
    int nd = dst[e];
    float4 a = *(const float4*)&g_g[ns * D + d4 * 4];
    float4 c = *(const float4*)&g_g[nd * D + d4 * 4];
    float4 o;
    o.x = 0.5f * (a.x + c.x);
    o.y = 0.5f * (a.y + c.y);
    o.z = 0.5f * (a.z + c.z);
    o.w = 0.5f * (a.w + c.w);
    st_cs_v4(&out[t], o);                            // streaming store
}

// ---------------------------------------------------------------------------
// Launch
// ---------------------------------------------------------------------------
extern "C" void kernel_launch(void* const* d_in, const int* in_sizes, int n_in,
                              void* d_out, int out_size) {
    const float* edge_feats = (const float*)d_in[0];
    const int*   src        = (const int*)d_in[1];
    const int*   dst        = (const int*)d_in[2];
    const float* W          = (const float*)d_in[3];
    const float* b          = (const float*)d_in[4];

    const int E   = in_sizes[1];
    const int TPB = 256;

    const int node_v4      = N_NODES * D4;           // 400K
    const int node_threads = N_NODES * 32;           // warp per node
    const int edge_v4      = E * D4;                 // 12.8M

    k_zero<<<(node_v4 + TPB - 1) / TPB, TPB>>>(b);
    k_scatter_feats<<<(edge_v4 + TPB - 1) / TPB, TPB>>>(
        (const float4*)edge_feats, dst, E);
    k_norm_gemm<<<(node_threads + TPB - 1) / TPB, TPB>>>(W);
    k_gather_scatter<<<(edge_v4 + TPB - 1) / TPB, TPB>>>(src, dst, E);
    k_edge_out<<<(edge_v4 + TPB - 1) / TPB, TPB>>>(src, dst, (float4*)d_out, E);
}

// round 5
// speedup vs baseline: 1.7089x; 1.0550x over previous
#include <cuda_runtime.h>
#include <cuda_bf16.h>

#define N_NODES 50000
#define D 32
#define D4 8

// Scratch (device globals — no allocation allowed).
__device__ float g_seg[N_NODES * D];   // step1 accumulator -> 0.5*(m W^T) (in place)
__device__ float g_deg[N_NODES];       // in-degree
__device__ float g_g[N_NODES * D];     // init b/2, += 0.5*(m W^T)[src]

__device__ __forceinline__ void red_add_v4(float* ptr, float4 v) {
    asm volatile("red.global.add.v4.f32 [%0], {%1, %2, %3, %4};"
                 :: "l"(ptr), "f"(v.x), "f"(v.y), "f"(v.z), "f"(v.w)
                 : "memory");
}

__device__ __forceinline__ float4 ld_cs_v4(const float4* ptr) {
    float4 v;
    asm volatile("ld.global.cs.v4.f32 {%0, %1, %2, %3}, [%4];"
                 : "=f"(v.x), "=f"(v.y), "=f"(v.z), "=f"(v.w) : "l"(ptr));
    return v;
}

__device__ __forceinline__ void st_cs_v4(float4* ptr, float4 v) {
    asm volatile("st.global.cs.v4.f32 [%0], {%1, %2, %3, %4};"
                 :: "l"(ptr), "f"(v.x), "f"(v.y), "f"(v.z), "f"(v.w)
                 : "memory");
}

// ---------------------------------------------------------------------------
// K1: g_seg = 0, deg = 0, g_g rows = b/2 (bias+0.5 folded into init)
// ---------------------------------------------------------------------------
__global__ void k_zero(const float* __restrict__ b) {
    int i = blockIdx.x * blockDim.x + threadIdx.x;   // over N_NODES * D4
    if (i < N_NODES * D4) {
        ((float4*)g_seg)[i] = make_float4(0.f, 0.f, 0.f, 0.f);
        float4 bb = *(const float4*)&b[(i & 7) * 4];
        bb.x *= 0.5f; bb.y *= 0.5f; bb.z *= 0.5f; bb.w *= 0.5f;
        ((float4*)g_g)[i] = bb;
    }
    if (i < N_NODES) g_deg[i] = 0.0f;
}

// ---------------------------------------------------------------------------
// K2: seg_sum[dst] += ef[e]; deg[dst] += 1.  ILP=2: edges e and e+half.
// ef read with evict-first (.cs): zero-reuse 205MB stream, keep L2 for tables.
// ---------------------------------------------------------------------------
__global__ void k_scatter_feats(const float4* __restrict__ ef,
                                const int* __restrict__ dst, int E, int half) {
    int t = blockIdx.x * blockDim.x + threadIdx.x;   // over half * D4
    if (t >= half * D4) return;
    int e  = t >> 3;
    int d4 = t & 7;
    int e2 = e + half;

    float4 v0 = ld_cs_v4(&ef[e * D4 + d4]);
    int n0 = dst[e];
    if (e2 < E) {
        float4 v1 = ld_cs_v4(&ef[e2 * D4 + d4]);
        int n1 = dst[e2];
        red_add_v4(&g_seg[n0 * D + d4 * 4], v0);
        red_add_v4(&g_seg[n1 * D + d4 * 4], v1);
        if (d4 == 0) {
            atomicAdd(&g_deg[n0], 1.0f);
            atomicAdd(&g_deg[n1], 1.0f);
        }
    } else {
        red_add_v4(&g_seg[n0 * D + d4 * 4], v0);
        if (d4 == 0) atomicAdd(&g_deg[n0], 1.0f);
    }
}

// ---------------------------------------------------------------------------
// K3: m = seg/max(deg,1); g_seg row <- 0.5 * (m @ W^T)  (warp per node)
// ---------------------------------------------------------------------------
__global__ void k_norm_gemm(const float* __restrict__ W) {
    __shared__ float Ws[D * (D + 1)];
    __shared__ float ms[8][D];
    for (int i = threadIdx.x; i < D * D; i += blockDim.x)
        Ws[(i / D) * (D + 1) + (i % D)] = W[i];
    __syncthreads();

    int w = (blockIdx.x * blockDim.x + threadIdx.x) >> 5;
    if (w >= N_NODES) return;
    int lane = threadIdx.x & 31;
    int wib  = (threadIdx.x >> 5) & 7;

    float inv = 1.0f / fmaxf(g_deg[w], 1.0f);
    ms[wib][lane] = g_seg[w * D + lane] * inv;
    __syncwarp();
    float acc = 0.0f;
#pragma unroll
    for (int k = 0; k < D; k++)
        acc = fmaf(ms[wib][k], Ws[lane * (D + 1) + k], acc);
    g_seg[w * D + lane] = 0.5f * acc;                // fold the final 0.5 here
}

// ---------------------------------------------------------------------------
// K4: g_g[dst] += g_seg[src]    ILP=2 (both tables L2-resident)
// ---------------------------------------------------------------------------
__global__ void k_gather_scatter(const int* __restrict__ src,
                                 const int* __restrict__ dst, int E, int half) {
    int t = blockIdx.x * blockDim.x + threadIdx.x;   // over half * D4
    if (t >= half * D4) return;
    int e  = t >> 3;
    int d4 = t & 7;
    int e2 = e + half;

    int ns0 = src[e];
    int nd0 = dst[e];
    float4 v0 = *(const float4*)&g_seg[ns0 * D + d4 * 4];
    if (e2 < E) {
        int ns1 = src[e2];
        int nd1 = dst[e2];
        float4 v1 = *(const float4*)&g_seg[ns1 * D + d4 * 4];
        red_add_v4(&g_g[nd0 * D + d4 * 4], v0);
        red_add_v4(&g_g[nd1 * D + d4 * 4], v1);
    } else {
        red_add_v4(&g_g[nd0 * D + d4 * 4], v0);
    }
}

// ---------------------------------------------------------------------------
// K5: out[e] = g_g[src[e]] + g_g[dst[e]]   (0.5 and b pre-folded)  ILP=2
// ---------------------------------------------------------------------------
__global__ void k_edge_out(const int* __restrict__ src,
                           const int* __restrict__ dst,
                           float4* __restrict__ out, int E, int half) {
    int t = blockIdx.x * blockDim.x + threadIdx.x;   // over half * D4
    if (t >= half * D4) return;
    int e  = t >> 3;
    int d4 = t & 7;
    int e2 = e + half;

    int ns0 = src[e];
    int nd0 = dst[e];
    float4 a0 = *(const float4*)&g_g[ns0 * D + d4 * 4];
    float4 c0 = *(const float4*)&g_g[nd0 * D + d4 * 4];
    float4 o0;
    o0.x = a0.x + c0.x; o0.y = a0.y + c0.y;
    o0.z = a0.z + c0.z; o0.w = a0.w + c0.w;

    if (e2 < E) {
        int ns1 = src[e2];
        int nd1 = dst[e2];
        float4 a1 = *(const float4*)&g_g[ns1 * D + d4 * 4];
        float4 c1 = *(const float4*)&g_g[nd1 * D + d4 * 4];
        float4 o1;
        o1.x = a1.x + c1.x; o1.y = a1.y + c1.y;
        o1.z = a1.z + c1.z; o1.w = a1.w + c1.w;
        st_cs_v4(&out[e * D4 + d4], o0);
        st_cs_v4(&out[e2 * D4 + d4], o1);
    } else {
        st_cs_v4(&out[e * D4 + d4], o0);
    }
}

// ---------------------------------------------------------------------------
// Launch
// ---------------------------------------------------------------------------
extern "C" void kernel_launch(void* const* d_in, const int* in_sizes, int n_in,
                              void* d_out, int out_size) {
    const float* edge_feats = (const float*)d_in[0];
    const int*   src        = (const int*)d_in[1];
    const int*   dst        = (const int*)d_in[2];
    const float* W          = (const float*)d_in[3];
    const float* b          = (const float*)d_in[4];

    const int E    = in_sizes[1];
    const int half = (E + 1) / 2;
    const int TPB  = 256;

    const int node_v4      = N_NODES * D4;
    const int node_threads = N_NODES * 32;
    const int half_v4      = half * D4;

    k_zero<<<(node_v4 + TPB - 1) / TPB, TPB>>>(b);
    k_scatter_feats<<<(half_v4 + TPB - 1) / TPB, TPB>>>(
        (const float4*)edge_feats, dst, E, half);
    k_norm_gemm<<<(node_threads + TPB - 1) / TPB, TPB>>>(W);
    k_gather_scatter<<<(half_v4 + TPB - 1) / TPB, TPB>>>(src, dst, E, half);
    k_edge_out<<<(half_v4 + TPB - 1) / TPB, TPB>>>(src, dst, (float4*)d_out, E, half);
}